// round 6
// baseline (speedup 1.0000x reference)
#include <cuda_runtime.h>
#include <cstdint>

typedef unsigned long long ull;

#define NCH 128
#define HW  14
#define NJ  32
#define NT  896              // tiles: one slice-pair each
#define NBLK 444             // 148 SMs * 3 CTAs
#define THREADS 128

#define WS_FLOATS (NCH * 96)                     // ws[i*96 + 3*j + c], 48 KB
#define XS_F2     (NCH * 18)                     // rows stride 18 float2, slots 0..15 used
#define SMEM_BYTES (WS_FLOATS * 4 + XS_F2 * 8)   // 67584 B -> 3 CTAs/SM

__device__ __align__(16) float W3g[WS_FLOATS];
__device__ unsigned int g_ctr;

__global__ void prep_kernel(const float* __restrict__ W) {
    int idx = blockIdx.x * blockDim.x + threadIdx.x;
    if (idx == 0) g_ctr = NBLK;
    if (idx < WS_FLOATS) {
        int i = idx / 96, c = idx % 96;
        int j = c / 3, kk = c % 3;
        W3g[idx] = W[j * 384 + kk * 128 + i];    // W[j, kk, i]
    }
}

__device__ __forceinline__ ull pack2(float v) {
    ull r; asm("mov.b64 %0, {%1, %1};" : "=l"(r) : "f"(v)); return r;
}
__device__ __forceinline__ void fma2(ull& d, ull a, ull b) {
    asm("fma.rn.f32x2 %0, %1, %2, %0;" : "+l"(d) : "l"(a), "l"(b));
}
__device__ __forceinline__ void add2(ull& d, ull a) {
    asm("add.rn.f32x2 %0, %0, %1;" : "+l"(d) : "l"(a));
}
__device__ __forceinline__ float lo32(ull a) { return __uint_as_float((unsigned)a); }
__device__ __forceinline__ float hi32(ull a) { return __uint_as_float((unsigned)(a >> 32)); }

// Prefetch one tile's two x rows for channel i=t into registers.
__device__ __forceinline__ void stage_load(const float* __restrict__ x, int tile, int li,
                                           float2 (&b0)[7], float2 (&b1)[7]) {
    int s0 = tile * 2;
    int n = s0 / 14, h0 = s0 % 14;
    const float2* p0 = (const float2*)(x + ((n * NCH + li) * HW + h0) * HW);
    const float2* p1 = (const float2*)(x + ((n * NCH + li) * HW + h0 + 1) * HW);
#pragma unroll
    for (int m = 0; m < 7; ++m) { b0[m] = __ldcs(p0 + m); b1[m] = __ldcs(p1 + m); }
}

// Load one K-step's operands: 5 broadcast LDS.128 (X) + 6 scalar LDS.32 (W).
__device__ __forceinline__ void ld_step(const ull* xr, const float* wr,
                                        ull (&X)[10], float (&Wf)[6]) {
#pragma unroll
    for (int q = 0; q < 5; ++q) {
        ulonglong2 v = *(const ulonglong2*)(xr + 2 * q);
        X[2 * q] = v.x; X[2 * q + 1] = v.y;
    }
    Wf[0] = wr[0];  Wf[1] = wr[1];  Wf[2] = wr[2];
    Wf[3] = wr[48]; Wf[4] = wr[49]; Wf[5] = wr[50];
}

// 42 packed FMAs: 2 output channels x 7 w x (2 slices in f32x2 lanes).
// OFS: slot offset of this thread's w-window within X (0 for wh=0, 1 for wh=1).
template <int OFS>
__device__ __forceinline__ void compute(const ull (&X)[10], const float (&Wf)[6],
                                        ull (&acc)[14]) {
    ull W0 = pack2(Wf[0]), W1 = pack2(Wf[1]), W2 = pack2(Wf[2]);
    ull W3 = pack2(Wf[3]), W4 = pack2(Wf[4]), W5 = pack2(Wf[5]);
#pragma unroll
    for (int w = 0; w < 7; ++w) {
        fma2(acc[w],     W0, X[w + OFS]);
        fma2(acc[w],     W1, X[w + OFS + 1]);
        fma2(acc[w],     W2, X[w + OFS + 2]);
        fma2(acc[w + 7], W3, X[w + OFS]);
        fma2(acc[w + 7], W4, X[w + OFS + 1]);
        fma2(acc[w + 7], W5, X[w + OFS + 2]);
    }
}

template <int OFS>
__device__ __forceinline__ void run_loop(const ull* xr, const float* wr, ull (&acc)[14]) {
    ull X0[10], X1[10];
    float Wf0[6], Wf1[6];
    ld_step(xr, wr, X0, Wf0);
#pragma unroll 1
    for (int s = 0; s < 30; s += 2) {
        ld_step(xr + 18, wr + 96, X1, Wf1);
        compute<OFS>(X0, Wf0, acc);
        ld_step(xr + 36, wr + 192, X0, Wf0);
        compute<OFS>(X1, Wf1, acc);
        xr += 36; wr += 192;
    }
    ld_step(xr + 18, wr + 96, X1, Wf1);
    compute<OFS>(X0, Wf0, acc);
    compute<OFS>(X1, Wf1, acc);
}

__global__ void __launch_bounds__(THREADS, 3)
conv3_kernel(const float* __restrict__ x, float* __restrict__ out) {
    extern __shared__ float smem[];
    float*  ws = smem;                          // [128][96]
    float2* xs = (float2*)(smem + WS_FLOATS);   // [128 rows][18] slots 0..15
    ull* scratch = (ull*)xs;                    // reused for k-reduce (10752 B)
    __shared__ int s_next;

    const int t    = threadIdx.x;
    const int lane = t & 31;
    const int wid  = t >> 5;       // k-split warp: i in [32*wid, 32*wid+32)
    const int jj   = lane & 15;    // output channels jj and jj+16
    const int wh   = lane >> 4;    // w-half: w' = wh*7 + w

    // ---- stage W once per persistent CTA ----
    {
        const float4* src = (const float4*)W3g;
        float4* dst = (float4*)ws;
        for (int m = t; m < WS_FLOATS / 4; m += THREADS) dst[m] = src[m];
    }

    float2 b0[7], b1[7];
    int tile = blockIdx.x;
    stage_load(x, tile, t, b0, b1);

    while (tile < NT) {
        __syncthreads();                        // (A) prev reduce/readers done
        // ---- STS stage row t: slot p = 1 + ((w+1)%14) holds x[w]; 0/15 = pad ----
        {
            float2* row = xs + t * 18;
            row[0]  = make_float2(0.f, 0.f);
            row[15] = make_float2(0.f, 0.f);
#pragma unroll
            for (int w = 0; w < 14; ++w) {
                int p = (w == 13) ? 1 : (w + 2);
                float a = (w & 1) ? b0[w >> 1].y : b0[w >> 1].x;
                float b = (w & 1) ? b1[w >> 1].y : b1[w >> 1].x;
                row[p] = make_float2(a, b);
            }
        }
        if (t == 0) s_next = atomicAdd(&g_ctr, 1);
        __syncthreads();                        // (B) xs + s_next ready
        int nxt = s_next;
        if (nxt < NT) stage_load(x, nxt, t, b0, b1);   // overlaps compute

        // ---- compute 32 K-steps (i = 32*wid + s) ----
        ull acc[14];
#pragma unroll
        for (int a = 0; a < 14; ++a) acc[a] = 0ull;

        const ull*   xr = (const ull*)(xs + (wid * 32) * 18) + wh * 6;
        const float* wr = ws + (wid * 32) * 96 + 3 * jj;
        if (wh == 0) run_loop<0>(xr, wr, acc);
        else         run_loop<1>(xr, wr, acc);

        __syncthreads();                        // (C) xs reads done -> scratch ok
        if (wid != 0) {
            ull* sp = scratch + (wid - 1) * 448 + lane;
#pragma unroll
            for (int a = 0; a < 14; ++a) sp[a * 32] = acc[a];
        }
        __syncthreads();                        // (D) scratch ready
        if (wid == 0) {
#pragma unroll
            for (int a = 0; a < 14; ++a) {
                add2(acc[a], scratch[a * 32 + lane]);
                add2(acc[a], scratch[448 + a * 32 + lane]);
                add2(acc[a], scratch[896 + a * 32 + lane]);
            }
            // ---- write out with height-roll(+1): slice0 = lo lane, slice1 = hi ----
            int s0 = tile * 2;
            int n = s0 / 14, h0 = s0 % 14;           // h0 even <= 12
            int h2a = h0 + 1;                        // never wraps
            int h2b = (h0 + 2 == 14) ? 0 : h0 + 2;   // slice1 rolled
#pragma unroll
            for (int j2 = 0; j2 < 2; ++j2) {
                int j = jj + 16 * j2;
                float* opa = out + ((n * NJ + j) * HW + h2a) * HW + wh * 7;
                float* opb = out + ((n * NJ + j) * HW + h2b) * HW + wh * 7;
#pragma unroll
                for (int w = 0; w < 7; ++w) {
                    ull v = acc[j2 * 7 + w];
                    opa[w] = lo32(v);
                    opb[w] = hi32(v);
                }
            }
        }
        tile = nxt;
    }
}

extern "C" void kernel_launch(void* const* d_in, const int* in_sizes, int n_in,
                              void* d_out, int out_size) {
    const float* x = (const float*)d_in[0];   // (128,128,14,14) fp32
    const float* W = (const float*)d_in[1];   // (32,3,128) fp32
    float* out = (float*)d_out;               // (128,32,14,14) fp32

    prep_kernel<<<12, 1024>>>(W);

    cudaFuncSetAttribute(conv3_kernel,
                         cudaFuncAttributeMaxDynamicSharedMemorySize, SMEM_BYTES);
    conv3_kernel<<<NBLK, THREADS, SMEM_BYTES>>>(x, out);
}

// round 7
// speedup vs baseline: 1.1401x; 1.1401x over previous
#include <cuda_runtime.h>
#include <cstdint>

typedef unsigned long long ull;

#define NCH 128
#define HW  14
#define NJ  32
#define NT  1792             // tiles: 896 slice-pairs x 2 j-halves
#define NBLK 740             // 148 SMs * 5 CTAs
#define THREADS 128

#define WS_FLOATS (3 * NCH * 16)                 // half-j W: [kk][i][16], 24 KB
#define XS_FLOATS (2 * NCH * 16)                 // x: 256 rows (i*2+s) x 16 slots, 16 KB
#define SMEM_BYTES ((WS_FLOATS + XS_FLOATS) * 4) // 40960 -> 5 CTAs/SM

// Pre-transposed W halves: W3g[((jh*3+kk)*128+i)*16 + 2*jg + e] = W[16jh+2jg+e, kk, i]
__device__ __align__(16) float W3g[2 * WS_FLOATS];
__device__ unsigned int g_ctr;

__global__ void prep_kernel(const float* __restrict__ W) {
    int idx = blockIdx.x * blockDim.x + threadIdx.x;
    if (idx == 0) g_ctr = NBLK;
    if (idx < 2 * WS_FLOATS) {
        int e  = idx & 1;
        int jg = (idx >> 1) & 7;
        int i  = (idx >> 4) & 127;
        int kk = (idx >> 11) % 3;
        int jh = idx / 6144;
        W3g[idx] = W[(16 * jh + 2 * jg + e) * 384 + kk * 128 + i];
    }
}

__device__ __forceinline__ ull pack2(float v) {
    ull r; asm("mov.b64 %0, {%1, %1};" : "=l"(r) : "f"(v)); return r;
}
__device__ __forceinline__ void fma2(ull& d, ull a, ull b) {
    asm("fma.rn.f32x2 %0, %1, %2, %0;" : "+l"(d) : "l"(a), "l"(b));
}
__device__ __forceinline__ void add2(ull& d, ull a) {
    asm("add.rn.f32x2 %0, %0, %1;" : "+l"(d) : "l"(a));
}
__device__ __forceinline__ float lo32(ull a) { return __uint_as_float((unsigned)a); }
__device__ __forceinline__ float hi32(ull a) { return __uint_as_float((unsigned)(a >> 32)); }

// One K-step's operands: 3 broadcast LDS.128 + 3 broadcast LDS.64 (all conflict-free).
__device__ __forceinline__ void ld_step(const float* xr, const float* wr,
                                        float (&X)[12], ull (&Wp)[3]) {
    float4 a = *(const float4*)(xr);
    float4 b = *(const float4*)(xr + 4);
    float4 c = *(const float4*)(xr + 8);
    X[0]=a.x; X[1]=a.y; X[2]=a.z;  X[3]=a.w;
    X[4]=b.x; X[5]=b.y; X[6]=b.z;  X[7]=b.w;
    X[8]=c.x; X[9]=c.y; X[10]=c.z; X[11]=c.w;
    Wp[0] = *(const ull*)(wr);
    Wp[1] = *(const ull*)(wr + 2048);
    Wp[2] = *(const ull*)(wr + 4096);
}

template <int OFS>
__device__ __forceinline__ void compute(const float (&X)[12], const ull (&Wp)[3],
                                        ull (&acc)[7]) {
    ull xb[9];
#pragma unroll
    for (int m = 0; m < 9; ++m) xb[m] = pack2(X[OFS + m]);
#pragma unroll
    for (int w = 0; w < 7; ++w) {
        fma2(acc[w], Wp[0], xb[w]);
        fma2(acc[w], Wp[1], xb[w + 1]);
        fma2(acc[w], Wp[2], xb[w + 2]);
    }
}

// 32 K-steps (i = 32*k4 + s), explicit 2-stage pipeline.
template <int OFS>
__device__ __forceinline__ void run_loop(const float* xr, const float* wr, ull (&acc)[7]) {
    float X0[12], X1[12];
    ull Wp0[3], Wp1[3];
    ld_step(xr, wr, X0, Wp0);
#pragma unroll 1
    for (int s = 0; s < 30; s += 2) {
        ld_step(xr + 32, wr + 16, X1, Wp1);
        compute<OFS>(X0, Wp0, acc);
        ld_step(xr + 64, wr + 32, X0, Wp0);
        compute<OFS>(X1, Wp1, acc);
        xr += 64; wr += 32;
    }
    ld_step(xr + 32, wr + 16, X1, Wp1);
    compute<OFS>(X0, Wp0, acc);
    compute<OFS>(X1, Wp1, acc);
}

__global__ void __launch_bounds__(THREADS, 5)
conv3_kernel(const float* __restrict__ x, float* __restrict__ out) {
    extern __shared__ float smem[];
    float* ws = smem;                    // [3][128][16]
    float* xs = smem + WS_FLOATS;        // [256 rows][16]
    ull* scratch = (ull*)xs;             // reused for k4 reduce (5376 B)
    __shared__ int s_next;

    const int t    = threadIdx.x;
    const int lane = t & 31;
    const int k4   = t >> 5;             // warp owns i in [32*k4, 32*k4+32)
    const int jg   = lane & 7;           // j-pair within half
    const int wg   = (lane >> 3) & 1;    // w-half
    const int sl   = lane >> 4;          // slice within pair

    // staging roles
    const int pl2 = lane & 7;            // slot pair (2*pl2, 2*pl2+1)
    const int rr  = lane >> 3;           // 0..3: row within 4-row group

    int tile = blockIdx.x;
    int jh_cur = 0;
    // ---- stage W half 0 ----
    {
        const float4* src = (const float4*)W3g;
        float4* dst = (float4*)ws;
#pragma unroll
        for (int m = 0; m < WS_FLOATS / 4 / THREADS; ++m)
            dst[m * THREADS + t] = src[m * THREADS + t];
    }

    while (tile < NT) {
        const int jh = (tile >= 896) ? 1 : 0;
        const int sp = tile - jh * 896;
        const int n  = sp / 7;
        const int hp = sp % 7;           // slices: h0 = 2hp, h1 = 2hp+1

        if (jh != jh_cur) {              // re-stage W half (at most once per CTA)
            jh_cur = jh;
            const float4* src = (const float4*)(W3g + jh * WS_FLOATS);
            float4* dst = (float4*)ws;
#pragma unroll
            for (int m = 0; m < WS_FLOATS / 4 / THREADS; ++m)
                dst[m * THREADS + t] = src[m * THREADS + t];
        }
        __syncthreads();                 // (A) previous xs/scratch use done

        // ---- stage x: warp k4 fills rows [64*k4, 64*k4+64) ----
        // slot p holds xpad: p=0,15 -> 0; p in 1..14 -> x[(p-2) mod 14]
#pragma unroll 1
        for (int it = 0; it < 16; ++it) {
            int row = 64 * k4 + 4 * it + rr;
            int i = row >> 1, s = row & 1;
            int h = 2 * hp + s;
            const float* xp = x + ((n * NCH + i) * HW + h) * HW;
            float2 v;
            if (pl2 == 0)      v = make_float2(0.f, __ldcs(xp + 13));
            else if (pl2 == 7) v = make_float2(__ldcs(xp + 12), 0.f);
            else               v = __ldcs((const float2*)(xp + 2 * pl2 - 2));
            *(float2*)(xs + row * 16 + 2 * pl2) = v;   // banks 16*(row&1)+2*pl2: CF
        }
        if (t == 0) s_next = atomicAdd(&g_ctr, 1);
        __syncthreads();                 // (B) xs + s_next ready
        int nxt = s_next;

        // ---- compute ----
        ull acc[7];
#pragma unroll
        for (int a = 0; a < 7; ++a) acc[a] = 0ull;

        const float* xr = xs + (64 * k4 + sl) * 16 + wg * 4;
        const float* wr = ws + (32 * k4) * 16 + 2 * jg;
        if (wg == 0) run_loop<0>(xr, wr, acc);
        else         run_loop<3>(xr, wr, acc);

        __syncthreads();                 // (C) xs reads done -> scratch reuse ok
        if (k4 != 0) {
            ull* sp2 = scratch + (k4 - 1) * 224 + lane * 7;
#pragma unroll
            for (int a = 0; a < 7; ++a) sp2[a] = acc[a];
        }
        __syncthreads();                 // (D) partials ready
        if (k4 == 0) {
            const ull* r0 = scratch + lane * 7;
#pragma unroll
            for (int a = 0; a < 7; ++a) {
                add2(acc[a], r0[a]);
                add2(acc[a], r0[224 + a]);
                add2(acc[a], r0[448 + a]);
            }
            // write with height-roll(+1): s=0 -> h=2hp -> h2=2hp+1 (no wrap);
            // s=1 -> h=2hp+1 -> h2=2hp+2, wraps to 0 when hp==6
            int h2 = (sl == 0) ? (2 * hp + 1) : ((hp == 6) ? 0 : 2 * hp + 2);
            int j0 = 16 * jh + 2 * jg;
            float* op = out + ((n * NJ + j0) * HW + h2) * HW + 7 * wg;
#pragma unroll
            for (int w = 0; w < 7; ++w) {
                op[w]       = lo32(acc[w]);   // j0
                op[w + 196] = hi32(acc[w]);   // j0+1
            }
        }
        tile = nxt;
    }
}

extern "C" void kernel_launch(void* const* d_in, const int* in_sizes, int n_in,
                              void* d_out, int out_size) {
    const float* x = (const float*)d_in[0];   // (128,128,14,14) fp32
    const float* W = (const float*)d_in[1];   // (32,3,128) fp32
    float* out = (float*)d_out;               // (128,32,14,14) fp32

    prep_kernel<<<12, 1024>>>(W);

    cudaFuncSetAttribute(conv3_kernel,
                         cudaFuncAttributeMaxDynamicSharedMemorySize, SMEM_BYTES);
    conv3_kernel<<<NBLK, THREADS, SMEM_BYTES>>>(x, out);
}

// round 9
// speedup vs baseline: 1.8144x; 1.5915x over previous
#include <cuda_runtime.h>
#include <cstdint>

#define HW   14
#define NCH  128
#define NJ   32
#define NT   896             // tiles: 2 (n,h) slices each
#define NBLK 444             // 148 SMs * 3 CTAs
#define THREADS 64

#define A_STRIDE 132         // words per A row (128 + 4 pad) -> conflict-free ldmatrix
#define A_ROWS   34          // 32 slot-rows + 2 tap-overrun rows
#define A_WORDS  (A_ROWS * A_STRIDE)      // 4488
#define B_STRIDE 132
#define B_WORDS  (96 * B_STRIDE)          // 12672 (rows = kk*32 + j)
#define SMEM_BYTES ((A_WORDS + B_WORDS) * 4)   // 68640 -> 3 CTAs/SM

__device__ __align__(16) unsigned Wg[96 * 128];   // tf32 W, row (kk*32+j), col i
__device__ unsigned g_ctr;

__global__ void prep_kernel(const float* __restrict__ W) {
    int idx = blockIdx.x * blockDim.x + threadIdx.x;
    if (idx == 0) g_ctr = NBLK;
    if (idx < 96 * 128) {
        int i  = idx & 127;
        int j  = (idx >> 7) & 31;
        int kk = idx >> 12;
        unsigned b;
        asm("cvt.rna.tf32.f32 %0, %1;" : "=r"(b) : "f"(W[j * 384 + kk * 128 + i]));
        Wg[(kk * 32 + j) * 128 + i] = b;
    }
}

__device__ __forceinline__ uint32_t smem_u32(const void* p) {
    uint32_t a;
    asm("{ .reg .u64 t; cvta.to.shared.u64 t, %1; cvt.u32.u64 %0, t; }" : "=r"(a) : "l"(p));
    return a;
}
__device__ __forceinline__ void ldsm_x4(uint32_t addr, unsigned& r0, unsigned& r1,
                                        unsigned& r2, unsigned& r3) {
    asm volatile("ldmatrix.sync.aligned.m8n8.x4.shared.b16 {%0,%1,%2,%3}, [%4];"
                 : "=r"(r0), "=r"(r1), "=r"(r2), "=r"(r3) : "r"(addr));
}
__device__ __forceinline__ void ldsm_x2(uint32_t addr, unsigned& r0, unsigned& r1) {
    asm volatile("ldmatrix.sync.aligned.m8n8.x2.shared.b16 {%0,%1}, [%2];"
                 : "=r"(r0), "=r"(r1) : "r"(addr));
}
__device__ __forceinline__ void mma_tf32(float* c, unsigned a0, unsigned a1, unsigned a2,
                                         unsigned a3, unsigned b0, unsigned b1) {
    asm volatile("mma.sync.aligned.m16n8k8.row.col.f32.tf32.tf32.f32 "
                 "{%0,%1,%2,%3}, {%4,%5,%6,%7}, {%8,%9}, {%0,%1,%2,%3};"
                 : "+f"(c[0]), "+f"(c[1]), "+f"(c[2]), "+f"(c[3])
                 : "r"(a0), "r"(a1), "r"(a2), "r"(a3), "r"(b0), "r"(b1));
}

__global__ void __launch_bounds__(THREADS)
conv_mma_kernel(const float* __restrict__ x, float* __restrict__ out) {
    extern __shared__ unsigned sm[];
    unsigned* As = sm;                 // [34][132]
    unsigned* Bs = sm + A_WORDS;       // [96][132]
    __shared__ int s_next;

    const int t    = threadIdx.x;
    const int lane = t & 31;
    const int g    = t >> 5;           // warp = slice within tile, m-tile rows 16g..16g+15

    // ---- stage B once (persistent CTA): 96 rows x 128 words, uint4, CF ----
    for (int idx = t; idx < 96 * 32; idx += THREADS) {
        int row = idx >> 5, seg = idx & 31;
        ((uint4*)(Bs + row * B_STRIDE))[seg] = ((const uint4*)(Wg + row * 128))[seg];
    }
    // ---- zero the always-zero A rows: slots 0,15 of both groups + overrun 32,33 ----
    {
        const int zr[6] = {0, 15, 16, 31, 32, 33};
        for (int idx = t; idx < 6 * 128; idx += THREADS)
            As[zr[idx >> 7] * A_STRIDE + (idx & 127)] = 0;
    }
    __syncthreads();

    int tile = blockIdx.x;
    while (tile < NT) {
        // ---- stage A: row (16g+p) col i = tf32(xpad[slice g, ch i, slot p]) ----
        for (int idx = t; idx < 256; idx += THREADS) {
            int i = idx & 127, gg = idx >> 7;
            int slice = tile * 2 + gg;
            int n = slice / 14, h = slice % 14;
            const float* xp = x + ((n * NCH + i) * HW + h) * HW;
            unsigned* base = As + (16 * gg) * A_STRIDE + i;
#pragma unroll
            for (int m2 = 0; m2 < 7; ++m2) {
                float2 v = __ldcs((const float2*)(xp + 2 * m2));
                int w0 = 2 * m2;
                int p0 = w0 + 2;                     // even w never wraps
                int p1 = (w0 == 12) ? 1 : (w0 + 3);  // w=13 wraps to slot 1
                unsigned b0, b1;
                asm("cvt.rna.tf32.f32 %0, %1;" : "=r"(b0) : "f"(v.x));
                asm("cvt.rna.tf32.f32 %0, %1;" : "=r"(b1) : "f"(v.y));
                base[p0 * A_STRIDE] = b0;            // banks (4p+i)%32: CF
                base[p1 * A_STRIDE] = b1;
            }
        }
        if (t == 0) s_next = atomicAdd(&g_ctr, 1);
        __syncthreads();                             // A ready + s_next visible
        int nxt = s_next;

        // ---- compute: D[16x32] per warp = 3 taps x 16 chunks x 4 n-tiles ----
        float acc[16];
#pragma unroll
        for (int a = 0; a < 16; ++a) acc[a] = 0.f;

        // ldmatrix lane addressing
        const uint32_t a_base = smem_u32(As) +
            (((16 * g + (lane & 15)) * A_STRIDE + 4 * (lane >> 4)) << 2);
        const uint32_t b_base = smem_u32(Bs) +
            (((lane & 7) * B_STRIDE + 4 * ((lane >> 3) & 1)) << 2);

#pragma unroll 1
        for (int kk = 0; kk < 3; ++kk) {
            uint32_t aa = a_base + kk * (A_STRIDE * 4);        // tap shift = +kk rows
            uint32_t bb = b_base + kk * (32 * B_STRIDE * 4);   // W tap block
#pragma unroll 4
            for (int q = 0; q < 16; ++q) {
                unsigned a0, a1, a2, a3;
                ldsm_x4(aa + q * 32, a0, a1, a2, a3);
#pragma unroll
                for (int tl = 0; tl < 4; ++tl) {
                    unsigned b0, b1;
                    ldsm_x2(bb + tl * (8 * B_STRIDE * 4) + q * 32, b0, b1);
                    mma_tf32(acc + 4 * tl, a0, a1, a2, a3, b0, b1);
                }
            }
        }
        __syncthreads();           // compute reads done -> next A stage may write

        // ---- epilogue: scatter D with height-roll(+1); rows w>=14 discarded ----
        {
            int slice = tile * 2 + g;
            int n = slice / 14, h = slice % 14;
            int h2 = (h + 1 == 14) ? 0 : h + 1;
            int r0 = lane >> 2, r1 = r0 + 8;
#pragma unroll
            for (int tl = 0; tl < 4; ++tl) {
                int j0 = 8 * tl + 2 * (lane & 3);
                float* o0 = out + ((n * NJ + j0) * HW + h2) * HW;
                o0[r0]       = acc[4 * tl + 0];
                o0[r0 + 196] = acc[4 * tl + 1];        // j0+1
                if (r1 < 14) {
                    o0[r1]       = acc[4 * tl + 2];
                    o0[r1 + 196] = acc[4 * tl + 3];
                }
            }
        }
        tile = nxt;
    }
}

extern "C" void kernel_launch(void* const* d_in, const int* in_sizes, int n_in,
                              void* d_out, int out_size) {
    const float* x = (const float*)d_in[0];   // (128,128,14,14) fp32
    const float* W = (const float*)d_in[1];   // (32,3,128) fp32
    float* out = (float*)d_out;               // (128,32,14,14) fp32

    prep_kernel<<<12, 1024>>>(W);

    cudaFuncSetAttribute(conv_mma_kernel,
                         cudaFuncAttributeMaxDynamicSharedMemorySize, SMEM_BYTES);
    conv_mma_kernel<<<NBLK, THREADS, SMEM_BYTES>>>(x, out);
}

// round 10
// speedup vs baseline: 1.9556x; 1.0778x over previous
#include <cuda_runtime.h>
#include <cstdint>

#define HW   14
#define NCH  128
#define NJ   32
#define NT   896             // tiles: 2 (n,h) slices each
#define NBLK 444             // 148 SMs * 3 CTAs
#define THREADS 128

#define A_STRIDE 132         // words per A row (128 + 4 pad) -> conflict-free ldmatrix
#define A_ROWS   34          // 32 slot-rows + 2 tap-overrun rows
#define A_WORDS  (A_ROWS * A_STRIDE)      // 4488
#define B_STRIDE 132
#define B_WORDS  (96 * B_STRIDE)          // 12672 (rows = kk*32 + j)
#define SMEM_BYTES ((A_WORDS + B_WORDS) * 4)   // 68640 -> 3 CTAs/SM

__device__ __align__(16) unsigned Wg[96 * 128];   // tf32 W, row (kk*32+j), col i
__device__ unsigned g_ctr;

__global__ void prep_kernel(const float* __restrict__ W) {
    int idx = blockIdx.x * blockDim.x + threadIdx.x;
    if (idx == 0) g_ctr = NBLK;
    if (idx < 96 * 128) {
        int i  = idx & 127;
        int j  = (idx >> 7) & 31;
        int kk = idx >> 12;
        unsigned b;
        asm("cvt.rna.tf32.f32 %0, %1;" : "=r"(b) : "f"(W[j * 384 + kk * 128 + i]));
        Wg[(kk * 32 + j) * 128 + i] = b;
    }
}

__device__ __forceinline__ uint32_t smem_u32(const void* p) {
    uint32_t a;
    asm("{ .reg .u64 t; cvta.to.shared.u64 t, %1; cvt.u32.u64 %0, t; }" : "=r"(a) : "l"(p));
    return a;
}
__device__ __forceinline__ void ldsm_x4(uint32_t addr, unsigned& r0, unsigned& r1,
                                        unsigned& r2, unsigned& r3) {
    asm volatile("ldmatrix.sync.aligned.m8n8.x4.shared.b16 {%0,%1,%2,%3}, [%4];"
                 : "=r"(r0), "=r"(r1), "=r"(r2), "=r"(r3) : "r"(addr));
}
__device__ __forceinline__ void mma_tf32(float* c, unsigned a0, unsigned a1, unsigned a2,
                                         unsigned a3, unsigned b0, unsigned b1) {
    asm volatile("mma.sync.aligned.m16n8k8.row.col.f32.tf32.tf32.f32 "
                 "{%0,%1,%2,%3}, {%4,%5,%6,%7}, {%8,%9}, {%0,%1,%2,%3};"
                 : "+f"(c[0]), "+f"(c[1]), "+f"(c[2]), "+f"(c[3])
                 : "r"(a0), "r"(a1), "r"(a2), "r"(a3), "r"(b0), "r"(b1));
}

// Prefetch one tile's x rows for channel i (both slices) into registers.
__device__ __forceinline__ void prefetch_x(const float* __restrict__ x, int tile, int i,
                                           float2 (&v)[2][7]) {
#pragma unroll
    for (int g = 0; g < 2; ++g) {
        int slice = tile * 2 + g;
        int n = slice / 14, h = slice % 14;
        const float2* xp = (const float2*)(x + ((n * NCH + i) * HW + h) * HW);
#pragma unroll
        for (int m2 = 0; m2 < 7; ++m2) v[g][m2] = __ldcs(xp + m2);
    }
}

__global__ void __launch_bounds__(THREADS)
conv_mma_kernel(const float* __restrict__ x, float* __restrict__ out) {
    extern __shared__ unsigned sm[];
    unsigned* As = sm;                 // [34][132]
    unsigned* Bs = sm + A_WORDS;       // [96][132]
    __shared__ int s_next;

    const int t    = threadIdx.x;
    const int lane = t & 31;
    const int wid  = t >> 5;
    const int g    = wid & 1;          // slice within tile (m-rows 16g..16g+15)
    const int nh   = wid >> 1;         // j-half: j in [16*nh, 16*nh+16)

    // ---- stage B once (persistent CTA): 96 rows x 128 words, uint4, CF ----
    for (int idx = t; idx < 96 * 32; idx += THREADS) {
        int row = idx >> 5, seg = idx & 31;
        ((uint4*)(Bs + row * B_STRIDE))[seg] = ((const uint4*)(Wg + row * 128))[seg];
    }
    // ---- zero the always-zero A rows: slots 0,15 of both groups + overrun 32,33 ----
    {
        const int zr[6] = {0, 15, 16, 31, 32, 33};
        for (int idx = t; idx < 6 * 128; idx += THREADS)
            As[zr[idx >> 7] * A_STRIDE + (idx & 127)] = 0;
    }

    // fragment base addresses (constant across tiles)
    const uint32_t a_base = smem_u32(As) +
        (((16 * g + (lane & 15)) * A_STRIDE + 4 * (lane >> 4)) << 2);
    const uint32_t b_base = smem_u32(Bs) +
        (((16 * nh + 8 * (lane >> 4) + (lane & 7)) * B_STRIDE + 4 * ((lane >> 3) & 1)) << 2);

    float2 v[2][7];
    int tile = blockIdx.x;
    prefetch_x(x, tile, t, v);

    while (tile < NT) {
        __syncthreads();                       // A writable (prev compute done / B staged)
        // ---- STS prefetched x -> A rows (16gg + p), col i = t; tf32-converted ----
        {
            unsigned* col = As + t;
#pragma unroll
            for (int gg = 0; gg < 2; ++gg) {
                unsigned* base = col + (16 * gg) * A_STRIDE;
#pragma unroll
                for (int m2 = 0; m2 < 7; ++m2) {
                    int w0 = 2 * m2;
                    int p0 = w0 + 2;                     // even w never wraps
                    int p1 = (w0 == 12) ? 1 : (w0 + 3);  // w=13 wraps to slot 1
                    unsigned b0, b1;
                    asm("cvt.rna.tf32.f32 %0, %1;" : "=r"(b0) : "f"(v[gg][m2].x));
                    asm("cvt.rna.tf32.f32 %0, %1;" : "=r"(b1) : "f"(v[gg][m2].y));
                    base[p0 * A_STRIDE] = b0;            // banks (4p+i)%32: CF
                    base[p1 * A_STRIDE] = b1;
                }
            }
        }
        if (t == 0) s_next = atomicAdd(&g_ctr, 1);
        __syncthreads();                       // A ready + s_next visible
        int nxt = s_next;
        if (nxt < NT) prefetch_x(x, nxt, t, v);   // LDG overlaps compute below

        // ---- compute: warp (g, nh) -> D[16m x 16j]; 3 taps x 16 k-chunks ----
        float acc[8];
#pragma unroll
        for (int a = 0; a < 8; ++a) acc[a] = 0.f;

#pragma unroll 1
        for (int kk = 0; kk < 3; ++kk) {
            uint32_t aa = a_base + kk * (A_STRIDE * 4);        // tap shift = +kk rows
            uint32_t bb = b_base + kk * (32 * B_STRIDE * 4);   // W tap block
#pragma unroll 4
            for (int q = 0; q < 16; ++q) {
                unsigned a0, a1, a2, a3, b0, b1, b2, b3;
                ldsm_x4(aa + q * 32, a0, a1, a2, a3);
                ldsm_x4(bb + q * 32, b0, b1, b2, b3);   // both 8-wide n-tiles of this j-half
                mma_tf32(acc,     a0, a1, a2, a3, b0, b1);
                mma_tf32(acc + 4, a0, a1, a2, a3, b2, b3);
            }
        }

        // ---- epilogue: scatter D with height-roll(+1); m rows >= 14 discarded ----
        {
            int slice = tile * 2 + g;
            int n = slice / 14, h = slice % 14;
            int h2 = (h + 1 == 14) ? 0 : h + 1;
            int r0 = lane >> 2, r1 = r0 + 8;
#pragma unroll
            for (int tl = 0; tl < 2; ++tl) {
                int j0 = 16 * nh + 8 * tl + 2 * (lane & 3);
                float* o0 = out + ((n * NJ + j0) * HW + h2) * HW;
                o0[r0]       = acc[4 * tl + 0];
                o0[r0 + 196] = acc[4 * tl + 1];        // j0+1
                if (r1 < 14) {
                    o0[r1]       = acc[4 * tl + 2];
                    o0[r1 + 196] = acc[4 * tl + 3];
                }
            }
        }
        tile = nxt;
    }
}

extern "C" void kernel_launch(void* const* d_in, const int* in_sizes, int n_in,
                              void* d_out, int out_size) {
    const float* x = (const float*)d_in[0];   // (128,128,14,14) fp32
    const float* W = (const float*)d_in[1];   // (32,3,128) fp32
    float* out = (float*)d_out;               // (128,32,14,14) fp32

    prep_kernel<<<12, 1024>>>(W);

    cudaFuncSetAttribute(conv_mma_kernel,
                         cudaFuncAttributeMaxDynamicSharedMemorySize, SMEM_BYTES);
    conv_mma_kernel<<<NBLK, THREADS, SMEM_BYTES>>>(x, out);
}

// round 11
// speedup vs baseline: 1.9972x; 1.0213x over previous
#include <cuda_runtime.h>
#include <cstdint>

#define HW   14
#define NCH  128
#define NJ   32
#define NT   896             // tiles: 2 (n,h) slices each
#define NBLK 296             // 148 SMs * 2 CTAs (each CTA = 2 half-pipelines)
#define THREADS 256

#define A_STRIDE 132         // words per A row (128 + 4 pad) -> conflict-free ldmatrix
#define A_ROWS   34          // 32 slot-rows + 2 tap-overrun rows
#define A_WORDS  (A_ROWS * A_STRIDE)      // 4488 per half
#define B_STRIDE 132
#define B_WORDS  (96 * B_STRIDE)          // 12672 (rows = kk*32 + j)
#define SMEM_BYTES ((B_WORDS + 2 * A_WORDS) * 4)   // 86592 B -> 2 CTAs/SM

__device__ __align__(16) unsigned Wg[96 * 128];   // tf32 W, row (kk*32+j), col i
__device__ unsigned g_ctr;

__global__ void prep_kernel(const float* __restrict__ W) {
    int idx = blockIdx.x * blockDim.x + threadIdx.x;
    if (idx == 0) g_ctr = 2 * NBLK;       // static ids 0..591 pre-assigned
    if (idx < 96 * 128) {
        int i  = idx & 127;
        int j  = (idx >> 7) & 31;
        int kk = idx >> 12;
        unsigned b;
        asm("cvt.rna.tf32.f32 %0, %1;" : "=r"(b) : "f"(W[j * 384 + kk * 128 + i]));
        Wg[(kk * 32 + j) * 128 + i] = b;
    }
}

__device__ __forceinline__ uint32_t smem_u32(const void* p) {
    uint32_t a;
    asm("{ .reg .u64 t; cvta.to.shared.u64 t, %1; cvt.u32.u64 %0, t; }" : "=r"(a) : "l"(p));
    return a;
}
__device__ __forceinline__ void barh(int id) {
    asm volatile("bar.sync %0, 128;" :: "r"(id) : "memory");
}
__device__ __forceinline__ void ldsm_x4(uint32_t addr, unsigned& r0, unsigned& r1,
                                        unsigned& r2, unsigned& r3) {
    asm volatile("ldmatrix.sync.aligned.m8n8.x4.shared.b16 {%0,%1,%2,%3}, [%4];"
                 : "=r"(r0), "=r"(r1), "=r"(r2), "=r"(r3) : "r"(addr));
}
__device__ __forceinline__ void mma_tf32(float* c, unsigned a0, unsigned a1, unsigned a2,
                                         unsigned a3, unsigned b0, unsigned b1) {
    asm volatile("mma.sync.aligned.m16n8k8.row.col.f32.tf32.tf32.f32 "
                 "{%0,%1,%2,%3}, {%4,%5,%6,%7}, {%8,%9}, {%0,%1,%2,%3};"
                 : "+f"(c[0]), "+f"(c[1]), "+f"(c[2]), "+f"(c[3])
                 : "r"(a0), "r"(a1), "r"(a2), "r"(a3), "r"(b0), "r"(b1));
}

// Prefetch one tile's x rows for channel i (both slices) into registers.
__device__ __forceinline__ void prefetch_x(const float* __restrict__ x, int tile, int i,
                                           float2 (&v)[2][7]) {
#pragma unroll
    for (int g = 0; g < 2; ++g) {
        int slice = tile * 2 + g;
        int n = slice / 14, h = slice % 14;
        const float2* xp = (const float2*)(x + ((n * NCH + i) * HW + h) * HW);
#pragma unroll
        for (int m2 = 0; m2 < 7; ++m2) v[g][m2] = __ldcs(xp + m2);
    }
}

__global__ void __launch_bounds__(THREADS)
conv_mma_kernel(const float* __restrict__ x, float* __restrict__ out) {
    extern __shared__ unsigned sm[];
    unsigned* Bs = sm;                        // [96][132]
    __shared__ int s_next[2];

    const int t    = threadIdx.x;
    const int lane = t & 31;
    const int hf   = t >> 7;                  // half-pipeline 0/1
    const int th   = t & 127;                 // thread within half
    const int wid2 = (t >> 5) & 3;            // warp within half
    const int g    = wid2 & 1;                // slice within tile
    const int nh   = wid2 >> 1;               // j-half

    unsigned* As = sm + B_WORDS + hf * A_WORDS;   // [34][132] per half

    // ---- stage B once (whole CTA): 96 rows x 128 words, uint4, CF ----
    for (int idx = t; idx < 96 * 32; idx += THREADS) {
        int row = idx >> 5, seg = idx & 31;
        ((uint4*)(Bs + row * B_STRIDE))[seg] = ((const uint4*)(Wg + row * 128))[seg];
    }
    // ---- zero the always-zero A rows of this half: slots 0,15 + overrun ----
    {
        const int zr[6] = {0, 15, 16, 31, 32, 33};
        for (int idx = th; idx < 6 * 128; idx += 128)
            As[zr[idx >> 7] * A_STRIDE + (idx & 127)] = 0;
    }
    __syncthreads();                          // B + A-zeros visible to both halves

    // fragment base addresses (constant across tiles)
    const uint32_t a_base = smem_u32(As) +
        (((16 * g + (lane & 15)) * A_STRIDE + 4 * (lane >> 4)) << 2);
    const uint32_t b_base = smem_u32(Bs) +
        (((16 * nh + 8 * (lane >> 4) + (lane & 7)) * B_STRIDE + 4 * ((lane >> 3) & 1)) << 2);

    float2 v[2][7];
    int cur = 2 * blockIdx.x + hf;            // static first tile, 0..591 < NT
    prefetch_x(x, cur, th, v);

    while (cur < NT) {
        barh(hf + 1);                         // (A) A-buffer free
        // ---- STS prefetched x -> A rows (16gg + p), col i = th ----
        {
            unsigned* col = As + th;
#pragma unroll
            for (int gg = 0; gg < 2; ++gg) {
                unsigned* base = col + (16 * gg) * A_STRIDE;
#pragma unroll
                for (int m2 = 0; m2 < 7; ++m2) {
                    int w0 = 2 * m2;
                    int p0 = w0 + 2;                     // even w never wraps
                    int p1 = (w0 == 12) ? 1 : (w0 + 3);  // w=13 wraps to slot 1
                    unsigned b0, b1;
                    asm("cvt.rna.tf32.f32 %0, %1;" : "=r"(b0) : "f"(v[gg][m2].x));
                    asm("cvt.rna.tf32.f32 %0, %1;" : "=r"(b1) : "f"(v[gg][m2].y));
                    base[p0 * A_STRIDE] = b0;            // banks (4p+i)%32: CF
                    base[p1 * A_STRIDE] = b1;
                }
            }
        }
        if (th == 0) s_next[hf] = atomicAdd(&g_ctr, 1);
        barh(hf + 1);                         // (B) A ready + s_next visible
        int nxt = s_next[hf];
        if (nxt < NT) prefetch_x(x, nxt, th, v);   // LDG overlaps compute below

        // ---- compute: warp (g, nh) -> D[16m x 16j]; 3 taps x 16 k-chunks ----
        float acc[8];
#pragma unroll
        for (int a = 0; a < 8; ++a) acc[a] = 0.f;

#pragma unroll 1
        for (int kk = 0; kk < 3; ++kk) {
            uint32_t aa = a_base + kk * (A_STRIDE * 4);        // tap shift = +kk rows
            uint32_t bb = b_base + kk * (32 * B_STRIDE * 4);   // W tap block
#pragma unroll 4
            for (int q = 0; q < 16; ++q) {
                unsigned a0, a1, a2, a3, b0, b1, b2, b3;
                ldsm_x4(aa + q * 32, a0, a1, a2, a3);
                ldsm_x4(bb + q * 32, b0, b1, b2, b3);
                mma_tf32(acc,     a0, a1, a2, a3, b0, b1);
                mma_tf32(acc + 4, a0, a1, a2, a3, b2, b3);
            }
        }

        // ---- epilogue: scatter D with height-roll(+1); m rows >= 14 discarded ----
        {
            int slice = cur * 2 + g;
            int n = slice / 14, h = slice % 14;
            int h2 = (h + 1 == 14) ? 0 : h + 1;
            int r0 = lane >> 2, r1 = r0 + 8;
#pragma unroll
            for (int tl = 0; tl < 2; ++tl) {
                int j0 = 16 * nh + 8 * tl + 2 * (lane & 3);
                float* o0 = out + ((n * NJ + j0) * HW + h2) * HW;
                o0[r0]       = acc[4 * tl + 0];
                o0[r0 + 196] = acc[4 * tl + 1];        // j0+1
                if (r1 < 14) {
                    o0[r1]       = acc[4 * tl + 2];
                    o0[r1 + 196] = acc[4 * tl + 3];
                }
            }
        }
        cur = nxt;
    }
}

extern "C" void kernel_launch(void* const* d_in, const int* in_sizes, int n_in,
                              void* d_out, int out_size) {
    const float* x = (const float*)d_in[0];   // (128,128,14,14) fp32
    const float* W = (const float*)d_in[1];   // (32,3,128) fp32
    float* out = (float*)d_out;               // (128,32,14,14) fp32

    prep_kernel<<<12, 1024>>>(W);

    cudaFuncSetAttribute(conv_mma_kernel,
                         cudaFuncAttributeMaxDynamicSharedMemorySize, SMEM_BYTES);
    conv_mma_kernel<<<NBLK, THREADS, SMEM_BYTES>>>(x, out);
}